// round 9
// baseline (speedup 1.0000x reference)
#include <cuda_runtime.h>

#define NN 100000
#define EE 1600000
#define ETOT (EE + NN)      // edges + self loops
#define FH 128              // heads*channels for layers 0/1
#define CC 32               // channels per head
#define NCLS 40
#define FULL 0xffffffffu

// ---------------- scratch (device globals; no allocation allowed) ------------
__device__ __align__(16) float g_h[NN * FH];      // transformed features (x @ W)
__device__ __align__(16) float g_feat[NN * FH];   // layer output features
__device__ __align__(16) float g_as[NN * 4];
__device__ __align__(16) float g_ad[NN * 4];
__device__ int   g_csrc[ETOT];        // CSR: src per edge, grouped by dst
__device__ int   g_deg[NN];
__device__ int   g_rowptr[NN + 1];
__device__ int   g_cursor[NN];
__device__ int   g_bsum[128];
__device__ int   g_boff[128];
__device__ int   g_is64;

#define SCAN_CHUNK 1024
#define NB ((NN + SCAN_CHUNK - 1) / SCAN_CHUNK)   // 98

static inline int cdiv(int a, int b) { return (a + b - 1) / b; }

// ================= edge ingestion + CSR build =================================
__global__ void detect_dtype(const int* __restrict__ e) {
    if (blockIdx.x != 0 || threadIdx.x != 0) return;
    int any = 0;
    for (int i = 0; i < 4096; i++) any |= e[2 * i + 1];
    g_is64 = (any == 0) ? 1 : 0;
}

// init deg to 1: the self-loop is pre-counted
__global__ void init_deg() {
    int i = blockIdx.x * blockDim.x + threadIdx.x;
    if (i < NN) g_deg[i] = 1;
}

__global__ void deg_count(const int* __restrict__ e) {
    int i = blockIdx.x * blockDim.x + threadIdx.x;
    if (i >= EE) return;
    int d = g_is64 ? e[2 * ((size_t)EE + i)] : e[EE + i];
    atomicAdd(&g_deg[d], 1);
}

__global__ void scan_a() {
    __shared__ int sm[256];
    int blk = blockIdx.x, tid = threadIdx.x;
    int base = blk * SCAN_CHUNK + tid * 4;
    int t = 0;
    #pragma unroll
    for (int i = 0; i < 4; i++) if (base + i < NN) t += g_deg[base + i];
    sm[tid] = t;
    __syncthreads();
    for (int o = 128; o > 0; o >>= 1) {
        if (tid < o) sm[tid] += sm[tid + o];
        __syncthreads();
    }
    if (tid == 0) g_bsum[blk] = sm[0];
}

__global__ void scan_b() {
    if (threadIdx.x != 0) return;
    int run = 0;
    for (int i = 0; i < NB; i++) { g_boff[i] = run; run += g_bsum[i]; }
}

__global__ void scan_c() {
    int blk = blockIdx.x, tid = threadIdx.x;
    int base = blk * SCAN_CHUNK + tid * 4;
    int v[4];
    #pragma unroll
    for (int i = 0; i < 4; i++) v[i] = (base + i < NN) ? g_deg[base + i] : 0;
    int tsum = v[0] + v[1] + v[2] + v[3];
    int lane = tid & 31, wid = tid >> 5;
    int inc = tsum;
    #pragma unroll
    for (int o = 1; o < 32; o <<= 1) {
        int t = __shfl_up_sync(FULL, inc, o);
        if (lane >= o) inc += t;
    }
    __shared__ int wsum[8];
    if (lane == 31) wsum[wid] = inc;
    __syncthreads();
    if (tid < 8) {
        int t = wsum[tid];
        #pragma unroll
        for (int o = 1; o < 8; o <<= 1) {
            int u = __shfl_up_sync(0xff, t, o);
            if (tid >= o) t += u;
        }
        wsum[tid] = t;
    }
    __syncthreads();
    int excl = inc - tsum + (wid > 0 ? wsum[wid - 1] : 0) + g_boff[blk];
    #pragma unroll
    for (int i = 0; i < 4; i++) {
        if (base + i < NN) { g_rowptr[base + i] = excl; g_cursor[base + i] = excl; }
        excl += v[i];
    }
    if (blk == 0 && tid == 0) g_rowptr[NN] = ETOT;
}

__global__ void scatter_csr(const int* __restrict__ e) {
    int i = blockIdx.x * blockDim.x + threadIdx.x;
    if (i >= ETOT) return;
    int s, d;
    if (i < EE) {
        if (g_is64) { s = e[2 * (size_t)i]; d = e[2 * ((size_t)EE + i)]; }
        else        { s = e[i];             d = e[EE + i]; }
    } else {
        s = i - EE; d = i - EE;
    }
    int pos = atomicAdd(&g_cursor[d], 1);
    g_csrc[pos] = s;
}

// ================= GEMM (big) + fused alpha =====================================
__global__ void gemm_big(const float* __restrict__ X, const float* __restrict__ W,
                         float* __restrict__ Y,
                         const float* __restrict__ as_, const float* __restrict__ ad_) {
    __shared__ __align__(16) float sxT[32 * 132];   // [k][row]
    __shared__ __align__(16) float sw[32 * 132];    // [k][col]
    const int tid = threadIdx.x;
    const int r0 = blockIdx.x * 128;
    const int rg = (tid >> 4) * 8;     // 16 row groups
    const int cg = (tid & 15) * 8;     // 16 col groups

    float acc[8][8];
    #pragma unroll
    for (int i = 0; i < 8; i++)
        #pragma unroll
        for (int j = 0; j < 8; j++) acc[i][j] = 0.0f;

    for (int kk = 0; kk < 128; kk += 32) {
        #pragma unroll
        for (int it = 0; it < 4; it++) {
            int idx = tid + it * 256;
            int row = idx >> 3;
            int kq  = idx & 7;
            int grow = r0 + row; if (grow >= NN) grow = NN - 1;
            float4 v = *(const float4*)&X[(size_t)grow * 128 + kk + kq * 4];
            sxT[(kq * 4 + 0) * 132 + row] = v.x;
            sxT[(kq * 4 + 1) * 132 + row] = v.y;
            sxT[(kq * 4 + 2) * 132 + row] = v.z;
            sxT[(kq * 4 + 3) * 132 + row] = v.w;
        }
        #pragma unroll
        for (int it = 0; it < 4; it++) {
            int idx = tid + it * 256;
            int k  = idx >> 5;
            int cq = idx & 31;
            *(float4*)&sw[k * 132 + cq * 4] =
                *(const float4*)&W[(size_t)(kk + k) * 128 + cq * 4];
        }
        __syncthreads();

        #pragma unroll
        for (int k = 0; k < 32; k++) {
            float4 a0 = *(const float4*)&sxT[k * 132 + rg];
            float4 a1 = *(const float4*)&sxT[k * 132 + rg + 4];
            float4 b0 = *(const float4*)&sw[k * 132 + cg];
            float4 b1 = *(const float4*)&sw[k * 132 + cg + 4];
            float ar[8] = {a0.x, a0.y, a0.z, a0.w, a1.x, a1.y, a1.z, a1.w};
            float bc[8] = {b0.x, b0.y, b0.z, b0.w, b1.x, b1.y, b1.z, b1.w};
            #pragma unroll
            for (int i = 0; i < 8; i++)
                #pragma unroll
                for (int j = 0; j < 8; j++)
                    acc[i][j] += ar[i] * bc[j];
        }
        __syncthreads();
    }

    #pragma unroll
    for (int i = 0; i < 8; i++) {
        int row = r0 + rg + i;
        if (row < NN) {
            float4 o0 = {acc[i][0], acc[i][1], acc[i][2], acc[i][3]};
            float4 o1 = {acc[i][4], acc[i][5], acc[i][6], acc[i][7]};
            *(float4*)&Y[(size_t)row * 128 + cg]     = o0;
            *(float4*)&Y[(size_t)row * 128 + cg + 4] = o1;
        }
    }

    // fused alpha: cols [cg, cg+8) lie inside head = cg>>5.
    float av[8], dv[8];
    #pragma unroll
    for (int j = 0; j < 8; j++) { av[j] = as_[cg + j]; dv[j] = ad_[cg + j]; }
    float ps[8], pd[8];
    #pragma unroll
    for (int i = 0; i < 8; i++) {
        float s = 0.0f, d = 0.0f;
        #pragma unroll
        for (int j = 0; j < 8; j++) { s += acc[i][j] * av[j]; d += acc[i][j] * dv[j]; }
        ps[i] = s; pd[i] = d;
    }
    #pragma unroll
    for (int i = 0; i < 8; i++) {
        ps[i] += __shfl_xor_sync(FULL, ps[i], 1);
        pd[i] += __shfl_xor_sync(FULL, pd[i], 1);
        ps[i] += __shfl_xor_sync(FULL, ps[i], 2);
        pd[i] += __shfl_xor_sync(FULL, pd[i], 2);
    }
    if ((tid & 3) == 0) {
        int head = (tid & 15) >> 2;
        #pragma unroll
        for (int i = 0; i < 8; i++) {
            int row = r0 + rg + i;
            if (row < NN) {
                g_as[row * 4 + head] = ps[i];
                g_ad[row * 4 + head] = pd[i];
            }
        }
    }
}

// ================= GEMM (small) + fused alpha: Y[N,32] = X @ W[128,32] =========
__global__ void gemm_small(const float* __restrict__ X, const float* __restrict__ W,
                           float* __restrict__ Y,
                           const float* __restrict__ as_, const float* __restrict__ ad_) {
    constexpr int SXP = 68;
    constexpr int SWP = 36;
    __shared__ __align__(16) float sxT[64 * SXP];
    __shared__ __align__(16) float sw[64 * SWP];
    const int tid = threadIdx.x;
    const int r0 = blockIdx.x * 64;

    const int rg = (tid >> 4) * 4;
    const int cg = (tid & 15) * 2;
    float acc[4][2];
    #pragma unroll
    for (int i = 0; i < 4; i++) { acc[i][0] = 0.0f; acc[i][1] = 0.0f; }

    for (int kk = 0; kk < 128; kk += 64) {
        for (int idx = tid; idx < 64 * 64; idx += 256) {
            int k = idx & 63;
            int r = idx >> 6;
            int row = r0 + r; if (row >= NN) row = NN - 1;
            sxT[k * SXP + r] = X[(size_t)row * 128 + kk + k];
        }
        for (int idx = tid; idx < 64 * 8; idx += 256) {
            int k = idx / 8;
            int jq = (idx % 8) * 4;
            *(float4*)&sw[k * SWP + jq] =
                *(const float4*)&W[(size_t)(kk + k) * 32 + jq];
        }
        __syncthreads();

        #pragma unroll 8
        for (int k = 0; k < 64; k++) {
            float4 a = *(const float4*)&sxT[k * SXP + rg];
            float2 b = *(const float2*)&sw[k * SWP + cg];
            acc[0][0] += a.x * b.x; acc[0][1] += a.x * b.y;
            acc[1][0] += a.y * b.x; acc[1][1] += a.y * b.y;
            acc[2][0] += a.z * b.x; acc[2][1] += a.z * b.y;
            acc[3][0] += a.w * b.x; acc[3][1] += a.w * b.y;
        }
        __syncthreads();
    }

    #pragma unroll
    for (int i = 0; i < 4; i++) {
        int row = r0 + rg + i;
        if (row < NN) {
            float2 o = {acc[i][0], acc[i][1]};
            *(float2*)&Y[(size_t)row * 32 + cg] = o;
        }
    }

    float a0 = as_[cg], a1 = as_[cg + 1];
    float d0 = ad_[cg], d1 = ad_[cg + 1];
    float ps[4], pd[4];
    #pragma unroll
    for (int i = 0; i < 4; i++) {
        ps[i] = acc[i][0] * a0 + acc[i][1] * a1;
        pd[i] = acc[i][0] * d0 + acc[i][1] * d1;
    }
    #pragma unroll
    for (int o = 1; o < 16; o <<= 1) {
        #pragma unroll
        for (int i = 0; i < 4; i++) {
            ps[i] += __shfl_xor_sync(FULL, ps[i], o);
            pd[i] += __shfl_xor_sync(FULL, pd[i], o);
        }
    }
    if ((tid & 15) == 0) {
        #pragma unroll
        for (int i = 0; i < 4; i++) {
            int row = r0 + rg + i;
            if (row < NN) { g_as[row] = ps[i]; g_ad[row] = pd[i]; }
        }
    }
}

// ====== merged segment-softmax + pull aggregation: ONE warp per node ===========
// pass 1: per-head max over in-edges (float4 gather of g_as).
// pass 2: recompute w = exp(leaky(as+ad)-m) per edge, accumulate sum(w*row) and
//         den simultaneously; normalize + bias + relu at the end. No g_e array.
__device__ __forceinline__ float leaky(float x) { return x > 0.0f ? x : 0.2f * x; }

template<int HH>
__global__ void csr_softagg(const float* __restrict__ hf,
                            const float* __restrict__ bias) {
    int n = (blockIdx.x * blockDim.x + threadIdx.x) >> 5;
    int lane = threadIdx.x & 31;
    if (n >= NN) return;
    int off = g_rowptr[n];
    int end = g_rowptr[n + 1];

    if constexpr (HH == 4) {
        const int head = lane >> 3;
        // ---- pass 1: per-head max ----
        float mx = -1e30f, my = -1e30f, mz = -1e30f, mw = -1e30f;
        for (int p = off + lane; p < end; p += 32) {
            int s = __ldg(&g_csrc[p]);
            float4 a = *(const float4*)&g_as[s * 4];
            mx = fmaxf(mx, a.x); my = fmaxf(my, a.y);
            mz = fmaxf(mz, a.z); mw = fmaxf(mw, a.w);
        }
        #pragma unroll
        for (int o = 16; o >= 1; o >>= 1) {
            mx = fmaxf(mx, __shfl_xor_sync(FULL, mx, o));
            my = fmaxf(my, __shfl_xor_sync(FULL, my, o));
            mz = fmaxf(mz, __shfl_xor_sync(FULL, mz, o));
            mw = fmaxf(mw, __shfl_xor_sync(FULL, mw, o));
        }
        float4 adv = *(const float4*)&g_ad[n * 4];
        // leaky monotone + ad const per node: max leaky(as+ad) = leaky(max as + ad)
        mx = leaky(mx + adv.x); my = leaky(my + adv.y);
        mz = leaky(mz + adv.z); mw = leaky(mw + adv.w);
        float mh   = head == 0 ? mx : head == 1 ? my : head == 2 ? mz : mw;
        float adh  = head == 0 ? adv.x : head == 1 ? adv.y : head == 2 ? adv.z : adv.w;

        // ---- pass 2: weighted row accumulation + den ----
        float4 acc = {0.0f, 0.0f, 0.0f, 0.0f};
        float den = 0.0f;
        #pragma unroll 2
        for (int p = off; p < end; p++) {
            int s = __ldg(&g_csrc[p]);                       // warp-uniform
            float a = __ldg(&g_as[s * 4 + head]);            // 1 sector / warp
            float w = __expf(leaky(a + adh) - mh);
            den += w;                                        // identical within head
            const float4 v = *(const float4*)&hf[(size_t)s * 128 + lane * 4];
            acc.x += w * v.x; acc.y += w * v.y;
            acc.z += w * v.z; acc.w += w * v.w;
        }
        float inv = 1.0f / (den + 1e-16f);
        float4 bv = *(const float4*)&bias[lane * 4];
        float4 o;
        o.x = fmaxf(acc.x * inv + bv.x, 0.0f);
        o.y = fmaxf(acc.y * inv + bv.y, 0.0f);
        o.z = fmaxf(acc.z * inv + bv.z, 0.0f);
        o.w = fmaxf(acc.w * inv + bv.w, 0.0f);
        *(float4*)&g_feat[(size_t)n * 128 + lane * 4] = o;
    } else {
        // ---- pass 1: max ----
        float m = -1e30f;
        for (int p = off + lane; p < end; p += 32)
            m = fmaxf(m, __ldg(&g_as[g_csrc[p]]));
        #pragma unroll
        for (int o = 16; o >= 1; o >>= 1) m = fmaxf(m, __shfl_xor_sync(FULL, m, o));
        float adh = g_ad[n];
        m = leaky(m + adh);
        // ---- pass 2 ----
        float acc = 0.0f, den = 0.0f;
        #pragma unroll 2
        for (int p = off; p < end; p++) {
            int s = __ldg(&g_csrc[p]);
            float w = __expf(leaky(__ldg(&g_as[s]) + adh) - m);
            den += w;
            acc += w * hf[(size_t)s * 32 + lane];
        }
        float inv = 1.0f / (den + 1e-16f);
        float v = acc * inv + bias[lane];
        g_feat[(size_t)n * 32 + lane] = v > 0.0f ? v : 0.0f;
    }
}

// ================= final linear 32 -> 40 =======================================
__global__ void final_linear(const float* __restrict__ xin,
                             const float* __restrict__ w,
                             const float* __restrict__ b,
                             float* __restrict__ out) {
    __shared__ float swt[32 * 40];
    __shared__ float sxr[64 * 33];
    int tid = threadIdx.x;
    int n0 = blockIdx.x * 64;
    for (int i = tid; i < 32 * 40; i += 256) swt[i] = w[i];
    for (int i = tid; i < 64 * 32; i += 256) {
        int n = i >> 5, c = i & 31;
        int gn = n0 + n;
        sxr[n * 33 + c] = (gn < NN) ? xin[(size_t)gn * 32 + c] : 0.0f;
    }
    __syncthreads();
    int nl = tid >> 2;
    int j0 = (tid & 3) * 10;
    int gn = n0 + nl;
    if (gn >= NN) return;
    float acc[10];
    #pragma unroll
    for (int j = 0; j < 10; j++) acc[j] = b[j0 + j];
    #pragma unroll
    for (int k = 0; k < 32; k++) {
        float xv = sxr[nl * 33 + k];
        #pragma unroll
        for (int j = 0; j < 10; j++) acc[j] += xv * swt[k * 40 + j0 + j];
    }
    #pragma unroll
    for (int j = 0; j < 10; j++) out[(size_t)gn * 40 + j0 + j] = acc[j];
}

// ================= launch ======================================================
extern "C" void kernel_launch(void* const* d_in, const int* in_sizes, int n_in,
                              void* d_out, int out_size) {
    const float* x   = (const float*)d_in[0];
    const int*   ei  = (const int*)d_in[1];
    const float* W0  = (const float*)d_in[2];
    const float* as0 = (const float*)d_in[3];
    const float* ad0 = (const float*)d_in[4];
    const float* b0  = (const float*)d_in[5];
    const float* W1  = (const float*)d_in[6];
    const float* as1 = (const float*)d_in[7];
    const float* ad1 = (const float*)d_in[8];
    const float* b1  = (const float*)d_in[9];
    const float* W2  = (const float*)d_in[10];
    const float* as2 = (const float*)d_in[11];
    const float* ad2 = (const float*)d_in[12];
    const float* b2  = (const float*)d_in[13];
    const float* lw  = (const float*)d_in[14];
    const float* lb  = (const float*)d_in[15];
    float* out = (float*)d_out;

    float *p_h, *p_feat;
    cudaGetSymbolAddress((void**)&p_h,    g_h);
    cudaGetSymbolAddress((void**)&p_feat, g_feat);

    const int T = 256;
    const int WPB = T / 32;          // warps per block

    // ---- CSR build (once) ----
    detect_dtype<<<1, 32>>>(ei);
    init_deg<<<cdiv(NN, T), T>>>();
    deg_count<<<cdiv(EE, T), T>>>(ei);
    scan_a<<<NB, 256>>>();
    scan_b<<<1, 32>>>();
    scan_c<<<NB, 256>>>();
    scatter_csr<<<cdiv(ETOT, T), T>>>(ei);

    // ---- layer 0: 128 -> 4x32, concat ----
    gemm_big<<<cdiv(NN, 128), 256>>>(x, W0, p_h, as0, ad0);
    csr_softagg<4><<<cdiv(NN, WPB), T>>>(p_h, b0);

    // ---- layer 1: 128 -> 4x32, concat ----
    gemm_big<<<cdiv(NN, 128), 256>>>(p_feat, W1, p_h, as1, ad1);
    csr_softagg<4><<<cdiv(NN, WPB), T>>>(p_h, b1);

    // ---- layer 2: 128 -> 32, heads=1, mean(=identity) ----
    gemm_small<<<cdiv(NN, 64), 256>>>(p_feat, W2, p_h, as2, ad2);
    csr_softagg<1><<<cdiv(NN, WPB), T>>>(p_h, b2);

    // ---- final linear 32 -> 40 ----
    final_linear<<<cdiv(NN, 64), T>>>(p_feat, lw, lb, out);
}